// round 8
// baseline (speedup 1.0000x reference)
#include <cuda_runtime.h>

// Problem constants
#define NN   4096
#define DD   2048
#define CC   128
#define D4   (DD/4)          // 512 float4 per row
#define MTOT 256             // stacked rows: 0..127 = CR, 128..255 = CT
#define MT   32              // gram m-tile per block
#define KS   32              // k slices
#define KSL  64              // k per slice (KS*KSL == DD)

// ---------------- device scratch (no allocation allowed) ----------------
__device__ int   g_cnt[CC];
__device__ float g_C  [MTOT * DD];       // class means [m][k]: CR rows then CT rows
__device__ float g_Ct [DD * MTOT];       // transposed [k][m]   (2 MB)
__device__ float g_CMt[DD * CC];         // 0.5*(CR+CT) [k][c]  (1 MB)
__device__ float g_nPart[4][3][CC];      // per-col-quarter norm partials (R,T,M)
__device__ float g_P2[KS][MTOT * CC];    // Gram K-partials, fixed slots (4 MB)
__device__ float g_la2[2 * CC];          // per (half, class-row) loss partials
__device__ int   g_ctr = 0;              // last-block counter (self-resetting)

// ---------------- f32x2 helpers (FFMA2 path) ----------------
__device__ __forceinline__ unsigned long long pack2(float x, float y) {
    unsigned long long r;
    asm("mov.b64 %0, {%1, %2};" : "=l"(r) : "f"(x), "f"(y));
    return r;
}
__device__ __forceinline__ unsigned long long fma2(unsigned long long a,
                                                   unsigned long long b,
                                                   unsigned long long c) {
    unsigned long long d;
    asm("fma.rn.f32x2 %0, %1, %2, %3;" : "=l"(d) : "l"(a), "l"(b), "l"(c));
    return d;
}
__device__ __forceinline__ float2 unpack2(unsigned long long v) {
    float2 f;
    asm("mov.b64 {%0, %1}, %2;" : "=f"(f.x), "=f"(f.y) : "l"(v));
    return f;
}

// ---------------- K1: fused warp-scan classlist + per-class means + norms -----
// grid (CC, 4), 128 threads. Warp-local scans (no block syncs in the scan loop),
// then deterministic concat. Carries the mandatory 64MB read.
__global__ void __launch_bounds__(128) k_means(const float* __restrict__ m1,
                                               const float* __restrict__ m2,
                                               const int*   __restrict__ targets) {
    int c = blockIdx.x, y = blockIdx.y, tid = threadIdx.x;
    int lane = tid & 31, warp = tid >> 5;

    __shared__ int s_list[4][1024];   // per-warp candidate lists (worst-case safe)
    __shared__ int s_cnt[4];
    __shared__ int s_idx[NN];

    // warp w scans targets[w*1024 .. +1024) independently — no block barriers
    {
        int base = warp * 1024;
        int cntw = 0;
        unsigned lt = (1u << lane) - 1u;
        #pragma unroll 4
        for (int j = 0; j < 32; j++) {
            int i = base + j * 32 + lane;
            int t = targets[i];
            bool flag = (t == c);
            unsigned mask = __ballot_sync(0xffffffffu, flag);
            if (flag) s_list[warp][cntw + __popc(mask & lt)] = i;
            cntw += __popc(mask);
        }
        if (lane == 0) s_cnt[warp] = cntw;
    }
    __syncthreads();

    int cw0 = s_cnt[0], cw1 = s_cnt[1], cw2 = s_cnt[2], cw3 = s_cnt[3];
    int cnt = cw0 + cw1 + cw2 + cw3;
    if (cnt > NN) cnt = NN;
    {   // deterministic concat: warp w copies its list to its fixed offset
        int off = (warp > 0 ? cw0 : 0) + (warp > 1 ? cw1 : 0) + (warp > 2 ? cw2 : 0);
        int n = s_cnt[warp];
        for (int i = lane; i < n; i += 32) s_idx[off + i] = s_list[warp][i];
    }
    __syncthreads();

    // gather: this block owns 128 consecutive float4 columns
    int col4 = y * 128 + tid;     // 0..511
    const float4* __restrict__ m1v = (const float4*)m1;
    const float4* __restrict__ m2v = (const float4*)m2;

    float4 sR = make_float4(0.f, 0.f, 0.f, 0.f);
    float4 sT = make_float4(0.f, 0.f, 0.f, 0.f);
    int k = 0;
    for (; k + 8 <= cnt; k += 8) {
        #pragma unroll
        for (int u = 0; u < 8; u++) {
            int r = s_idx[k + u];
            float4 a = m1v[r * D4 + col4];
            float4 b = m2v[r * D4 + col4];
            sR.x += a.x; sR.y += a.y; sR.z += a.z; sR.w += a.w;
            sT.x += b.x; sT.y += b.y; sT.z += b.z; sT.w += b.w;
        }
    }
    for (; k < cnt; k++) {
        int r = s_idx[k];
        float4 a = m1v[r * D4 + col4];
        float4 b = m2v[r * D4 + col4];
        sR.x += a.x; sR.y += a.y; sR.z += a.z; sR.w += a.w;
        sT.x += b.x; sT.y += b.y; sT.z += b.z; sT.w += b.w;
    }

    float inv = 1.0f / (float)(cnt > 0 ? cnt : 1);
    float4 mr = make_float4(sR.x * inv, sR.y * inv, sR.z * inv, sR.w * inv);
    float4 mt = make_float4(sT.x * inv, sT.y * inv, sT.z * inv, sT.w * inv);
    float4 mm = make_float4(0.5f * (mr.x + mt.x), 0.5f * (mr.y + mt.y),
                            0.5f * (mr.z + mt.z), 0.5f * (mr.w + mt.w));

    ((float4*)g_C)[c * D4 + col4]        = mr;
    ((float4*)g_C)[(CC + c) * D4 + col4] = mt;

    // norm partials over this column quarter (fixed-tree reduce)
    float pR = mr.x * mr.x + mr.y * mr.y + mr.z * mr.z + mr.w * mr.w;
    float pT = mt.x * mt.x + mt.y * mt.y + mt.z * mt.z + mt.w * mt.w;
    float pM = mm.x * mm.x + mm.y * mm.y + mm.z * mm.z + mm.w * mm.w;
    __shared__ float r0[128], r1[128], r2[128];
    r0[tid] = pR; r1[tid] = pT; r2[tid] = pM;
    __syncthreads();
    for (int s = 64; s > 0; s >>= 1) {
        if (tid < s) { r0[tid] += r0[tid + s]; r1[tid] += r1[tid + s]; r2[tid] += r2[tid + s]; }
        __syncthreads();
    }
    if (tid == 0) {
        g_nPart[y][0][c] = r0[0];
        g_nPart[y][1][c] = r1[0];
        g_nPart[y][2][c] = r2[0];
        if (y == 0) g_cnt[c] = cnt;
    }
}

// ---------------- K2: paired-tile transpose; also emits CMt = 0.5(CR+CT) ------
// grid (DD/32 = 64 k-tiles, CC/32 = 4 m-pair-tiles), 256 threads.
__global__ void __launch_bounds__(256) k_T() {
    __shared__ float sR[32][33];
    __shared__ float sT[32][33];
    int kt = blockIdx.x, mt = blockIdx.y, tid = threadIdx.x;
    int mbase = mt * 32;

    const float4* __restrict__ c4 = (const float4*)g_C;
    int r  = tid >> 3;     // 0..31 (row within tile)
    int q4 = tid & 7;      // 0..7  (float4 within 32-float k window)
    float4 vR = c4[(mbase + r) * D4 + kt * 8 + q4];
    float4 vT = c4[(128 + mbase + r) * D4 + kt * 8 + q4];
    sR[r][q4 * 4 + 0] = vR.x; sR[r][q4 * 4 + 1] = vR.y;
    sR[r][q4 * 4 + 2] = vR.z; sR[r][q4 * 4 + 3] = vR.w;
    sT[r][q4 * 4 + 0] = vT.x; sT[r][q4 * 4 + 1] = vT.y;
    sT[r][q4 * 4 + 2] = vT.z; sT[r][q4 * 4 + 3] = vT.w;
    __syncthreads();

    int kk = tid >> 3;     // 0..31 (k within tile)
    int m4 = tid & 7;      // 0..7  (float4 of m)
    float4 wR = make_float4(sR[m4 * 4 + 0][kk], sR[m4 * 4 + 1][kk],
                            sR[m4 * 4 + 2][kk], sR[m4 * 4 + 3][kk]);
    float4 wT = make_float4(sT[m4 * 4 + 0][kk], sT[m4 * 4 + 1][kk],
                            sT[m4 * 4 + 2][kk], sT[m4 * 4 + 3][kk]);
    float4 wM = make_float4(0.5f * (wR.x + wT.x), 0.5f * (wR.y + wT.y),
                            0.5f * (wR.z + wT.z), 0.5f * (wR.w + wT.w));
    int krow = kt * 32 + kk;
    ((float4*)g_Ct)[krow * (MTOT / 4) + (mbase >> 2) + m4]         = wR;
    ((float4*)g_Ct)[krow * (MTOT / 4) + ((128 + mbase) >> 2) + m4] = wT;
    ((float4*)g_CMt)[krow * (CC / 4) + (mbase >> 2) + m4]          = wM;
}

// ---------------- K3: smem-tiled Gram with FFMA2: [256x128] = [CR;CT] * CmT ---
// grid (MTOT/MT = 8, KS = 32) = 256 blocks, 256 threads. 4x4 tile per thread,
// rows paired into f32x2 accumulators.
__global__ void __launch_bounds__(256) k_gram() {
    __shared__ float4 As4[KSL][9];     // [k][8 used], rows m0..m0+31
    __shared__ float4 Bs4[KSL][33];    // [k][32 used], all 128 cols

    int tid = threadIdx.x;
    int m0  = blockIdx.x * MT;
    int kb  = blockIdx.y * KSL;

    const float4* __restrict__ ct4 = (const float4*)g_Ct;
    #pragma unroll
    for (int i = 0; i < 2; i++) {
        int idx = tid + i * 256;            // 0..511
        int k = idx >> 3, j = idx & 7;
        As4[k][j] = ct4[(kb + k) * (MTOT / 4) + (m0 >> 2) + j];
    }
    const float4* __restrict__ cm4 = (const float4*)g_CMt;
    #pragma unroll
    for (int i = 0; i < 8; i++) {
        int idx = tid + i * 256;            // 0..2047
        int k = idx >> 5, q = idx & 31;
        Bs4[k][q] = cm4[(kb + k) * (CC / 4) + q];
    }
    __syncthreads();

    int tx = tid & 31;     // col group: cols tx*4..+3
    int ty = tid >> 5;     // row group: rows ty*4..+3 (warp-uniform -> broadcast)

    // acc2[c][p]: p=0 rows (0,1), p=1 rows (2,3) of this thread's 4x4 tile
    unsigned long long acc2[4][2];
    #pragma unroll
    for (int cJ = 0; cJ < 4; cJ++) { acc2[cJ][0] = 0ull; acc2[cJ][1] = 0ull; }

    #pragma unroll 8
    for (int k = 0; k < KSL; k++) {
        float4 a = As4[k][ty];
        float4 b = Bs4[k][tx];
        unsigned long long a01 = pack2(a.x, a.y);
        unsigned long long a23 = pack2(a.z, a.w);
        unsigned long long b0 = pack2(b.x, b.x);
        unsigned long long b1 = pack2(b.y, b.y);
        unsigned long long b2 = pack2(b.z, b.z);
        unsigned long long b3 = pack2(b.w, b.w);
        acc2[0][0] = fma2(a01, b0, acc2[0][0]);
        acc2[0][1] = fma2(a23, b0, acc2[0][1]);
        acc2[1][0] = fma2(a01, b1, acc2[1][0]);
        acc2[1][1] = fma2(a23, b1, acc2[1][1]);
        acc2[2][0] = fma2(a01, b2, acc2[2][0]);
        acc2[2][1] = fma2(a23, b2, acc2[2][1]);
        acc2[3][0] = fma2(a01, b3, acc2[3][0]);
        acc2[3][1] = fma2(a23, b3, acc2[3][1]);
    }

    float2 u00 = unpack2(acc2[0][0]), u01 = unpack2(acc2[0][1]);
    float2 u10 = unpack2(acc2[1][0]), u11 = unpack2(acc2[1][1]);
    float2 u20 = unpack2(acc2[2][0]), u21 = unpack2(acc2[2][1]);
    float2 u30 = unpack2(acc2[3][0]), u31 = unpack2(acc2[3][1]);

    float4* __restrict__ dst = (float4*)(&g_P2[blockIdx.y][0]);
    dst[(m0 + ty * 4 + 0) * (CC / 4) + tx] = make_float4(u00.x, u10.x, u20.x, u30.x);
    dst[(m0 + ty * 4 + 1) * (CC / 4) + tx] = make_float4(u00.y, u10.y, u20.y, u30.y);
    dst[(m0 + ty * 4 + 2) * (CC / 4) + tx] = make_float4(u01.x, u11.x, u21.x, u31.x);
    dst[(m0 + ty * 4 + 3) * (CC / 4) + tx] = make_float4(u01.y, u11.y, u21.y, u31.y);
}

// ---------------- K4: half-split loss, float4 + thread-level ks split ---------
// grid (CC, 2), 128 threads. thread = (ksg 0..3, b4 0..31). Each thread sums 8
// K-slices of one float4 b-group -> 8 independent LDG.128 (structural MLP=8).
__global__ void __launch_bounds__(128) k_loss(float* __restrict__ out) {
    int a    = blockIdx.x;
    int half = blockIdx.y;          // 0 = CR(G1), 1 = CT(G2)
    int tid  = threadIdx.x;
    int ksg  = tid >> 5;            // 0..3  (8 slices each)
    int b4   = tid & 31;            // float4 group over b
    int m    = half * CC + a;

    const float4* __restrict__ base = (const float4*)(&g_P2[0][m * CC]);
    // slice stride in float4: MTOT*CC/4
    float4 p = make_float4(0.f, 0.f, 0.f, 0.f);
    {
        float4 t0 = base[(ksg * 8 + 0) * (MTOT * CC / 4) + b4];
        float4 t1 = base[(ksg * 8 + 1) * (MTOT * CC / 4) + b4];
        float4 t2 = base[(ksg * 8 + 2) * (MTOT * CC / 4) + b4];
        float4 t3 = base[(ksg * 8 + 3) * (MTOT * CC / 4) + b4];
        float4 t4 = base[(ksg * 8 + 4) * (MTOT * CC / 4) + b4];
        float4 t5 = base[(ksg * 8 + 5) * (MTOT * CC / 4) + b4];
        float4 t6 = base[(ksg * 8 + 6) * (MTOT * CC / 4) + b4];
        float4 t7 = base[(ksg * 8 + 7) * (MTOT * CC / 4) + b4];
        p.x = ((t0.x + t1.x) + (t2.x + t3.x)) + ((t4.x + t5.x) + (t6.x + t7.x));
        p.y = ((t0.y + t1.y) + (t2.y + t3.y)) + ((t4.y + t5.y) + (t6.y + t7.y));
        p.z = ((t0.z + t1.z) + (t2.z + t3.z)) + ((t4.z + t5.z) + (t6.z + t7.z));
        p.w = ((t0.w + t1.w) + (t2.w + t3.w)) + ((t4.w + t5.w) + (t6.w + t7.w));
    }

    __shared__ float4 sP[4][32];
    __shared__ float  sred[32];
    sP[ksg][b4] = p;
    __syncthreads();

    if (tid < 32) {
        int bg = tid;                    // b-group: b = bg*4..+3
        float4 p0 = sP[0][bg], p1 = sP[1][bg], p2 = sP[2][bg], p3 = sP[3][bg];
        float G[4] = { (p0.x + p1.x) + (p2.x + p3.x),
                       (p0.y + p1.y) + (p2.y + p3.y),
                       (p0.z + p1.z) + (p2.z + p3.z),
                       (p0.w + p1.w) + (p2.w + p3.w) };

        float nA = 0.f;
        #pragma unroll
        for (int y = 0; y < 4; y++) nA += g_nPart[y][half][a];
        float wa = (float)g_cnt[a];

        float acc = 0.f;
        #pragma unroll
        for (int j = 0; j < 4; j++) {
            int b = bg * 4 + j;
            float nMb = 0.f;
            #pragma unroll
            for (int y = 0; y < 4; y++) nMb += g_nPart[y][2][b];
            float sq  = fmaxf(nA + nMb - 2.f * G[j], 1e-12f);
            float wgt = wa * (float)g_cnt[b];
            float term;
            if (a == b) {
                term = sq;              // label==1 half-term
            } else {
                term = 0.f;             // label==0 half-term
                if (sq < 0.0625f) {
                    float dd = sqrtf(sqrtf(sq) + 1e-10f);
                    float r  = fmaxf(0.5f - dd, 0.f);
                    term = r * r;
                }
            }
            acc += wgt * term;
        }
        sred[bg] = acc;
    }
    __syncthreads();
    if (tid < 16) sred[tid] += sred[tid + 16];
    __syncthreads();
    if (tid < 8)  sred[tid] += sred[tid + 8];
    __syncthreads();
    if (tid < 4)  sred[tid] += sred[tid + 4];
    __syncthreads();
    if (tid < 2)  sred[tid] += sred[tid + 2];
    __syncthreads();
    if (tid == 0) g_la2[half * CC + a] = sred[0] + sred[1];

    // last-block final reduce over 256 partials (deterministic fixed order)
    __shared__ int s_last;
    if (tid == 0) {
        __threadfence();
        int t = atomicAdd(&g_ctr, 1);
        s_last = (t == 2 * CC - 1) ? 1 : 0;
    }
    __syncthreads();
    if (s_last) {
        __shared__ float fin[128];
        fin[tid] = g_la2[tid] + g_la2[CC + tid];
        __syncthreads();
        for (int s = 64; s > 0; s >>= 1) {
            if (tid < s) fin[tid] += fin[tid + s];
            __syncthreads();
        }
        if (tid == 0) {
            out[0] = fin[0] * (1.0f / ((float)NN * (float)NN));
            g_ctr = 0;   // reset for next graph replay
        }
    }
}

// ---------------- launch ----------------
extern "C" void kernel_launch(void* const* d_in, const int* in_sizes, int n_in,
                              void* d_out, int out_size) {
    const float* m1 = (const float*)d_in[0];
    const float* m2 = (const float*)d_in[1];
    const int*   tg = (const int*)d_in[2];
    float* out = (float*)d_out;

    k_means<<<dim3(CC, 4), 128>>>(m1, m2, tg);
    k_T<<<dim3(DD / 32, CC / 32), 256>>>();
    k_gram<<<dim3(MTOT / MT, KS), 256>>>();
    k_loss<<<dim3(CC, 2), 128>>>(out);
}